// round 14
// baseline (speedup 1.0000x reference)
#include <cuda_runtime.h>
#include <cuda_fp16.h>

// HashEmbedding: out[t, d] = sum_{h=0..3} weight_table[x[t,h] + 513*h] * emb_table[x[t,h]>>1][d]
// x is int32.
// R14: R13 + PERMUTED smem table layout. Each row's 256 fp16 cols stored as
// [c0..c3, c128..c131, c4..c7, c132..c135, ...] so lane L's single 16-byte
// LDS.128 holds exactly the 8 cols needed for both coalesced float4 stores
// (cols L*4.. of each 128-col half). Gathers: 16 LDS.64 -> 8 LDS.128 per pair.
// R11 vs R13 proved the kernel is bound by memory-instruction count (identical
// mem ops, 2x different ALU, identical dur); this cuts mem ops 30 -> 22/pair.

#define NUM_HASHES 4
#define D 256
#define W_TABLE 2052           // 512*4 + 4
#define EMB_ROWS 256
#define BLOCK_THREADS 1024
#define WARPS_PER_BLOCK (BLOCK_THREADS / 32)
#define GRID_X 148

#define W_BYTES   (W_TABLE * 4)          // 8208 (half2 per entry)
#define EMB_BYTES (EMB_ROWS * D * 2)     // 131072

// smem byte offsets
#define OFF_W     0                      // half2[2052]
#define OFF_MBAR  8208
#define OFF_EMB   8320                   // 128-aligned
#define SMEM_BYTES (OFF_EMB + EMB_BYTES)

// Pre-converted tables (filled by convert kernel each replay).
__device__ __align__(16) __half2 g_wh2[W_TABLE];
__device__ __align__(16) __half2 g_emb_h2[EMB_ROWS * D / 2];   // PERMUTED layout

__global__ void convert_tables_kernel(const float* __restrict__ weight_table,
                                      const float* __restrict__ emb_table)
{
    const int i = blockIdx.x * blockDim.x + threadIdx.x;
    if (i < W_TABLE) {
        g_wh2[i] = __float2half2_rn(weight_table[i]);   // duplicated lanes
    }
    if (i < EMB_ROWS * D / 2) {
        const int row = i >> 7;           // 128 h2 per row
        const int cp  = i & 127;          // h2 index within row (orig col = 2*cp)
        const int c   = cp * 2;
        const float2 v = *reinterpret_cast<const float2*>(emb_table + row * D + c);
        // permuted h2 position within row: group g = (c%128)/4, half h = c/128,
        // pos2 = (c%4)/2  ->  g*4 + h*2 + pos2
        const int g    = (c & 127) >> 2;
        const int h    = c >> 7;
        const int pos2 = (c & 3) >> 1;
        g_emb_h2[row * 128 + g * 4 + h * 2 + pos2] = __floats2half2_rn(v.x, v.y);
    }
}

__global__ __launch_bounds__(BLOCK_THREADS, 1)
void hash_embedding_kernel(const int* __restrict__ x,
                           float* __restrict__ out,
                           int ntok)
{
    extern __shared__ char smem[];
    const __half2* s_wh  = reinterpret_cast<const __half2*>(smem + OFF_W);
    const char*    s_emb = smem + OFF_EMB;   // [256 rows][512 B permuted]

    const int tid = threadIdx.x;

    unsigned int smem_base;
    asm("{ .reg .u64 t; cvta.to.shared.u64 t, %1; cvt.u32.u64 %0, t; }"
        : "=r"(smem_base) : "l"(smem));

    // ---- async bulk-load both pre-converted tables ----
    if (tid == 0) {
        asm volatile("mbarrier.init.shared.b64 [%0], 1;"
                     :: "r"(smem_base + OFF_MBAR) : "memory");
        asm volatile("fence.proxy.async.shared::cta;" ::: "memory");
        asm volatile("mbarrier.arrive.expect_tx.shared.b64 _, [%0], %1;"
                     :: "r"(smem_base + OFF_MBAR),
                        "r"((unsigned)(W_BYTES + EMB_BYTES)) : "memory");
        asm volatile(
            "cp.async.bulk.shared::cta.global.mbarrier::complete_tx::bytes "
            "[%0], [%1], %2, [%3];"
            :: "r"(smem_base + OFF_W), "l"(g_wh2),
               "r"((unsigned)W_BYTES), "r"(smem_base + OFF_MBAR) : "memory");
        asm volatile(
            "cp.async.bulk.shared::cta.global.mbarrier::complete_tx::bytes "
            "[%0], [%1], %2, [%3];"
            :: "r"(smem_base + OFF_EMB), "l"(g_emb_h2),
               "r"((unsigned)EMB_BYTES), "r"(smem_base + OFF_MBAR) : "memory");
    }
    __syncthreads();   // mbarrier init visible to all before waiting

    {
        unsigned int mbar = smem_base + OFF_MBAR;
        unsigned int done;
        asm volatile(
            "{\n\t.reg .pred p;\n\t"
            "mbarrier.try_wait.parity.acquire.cta.shared::cta.b64 p, [%1], 0;\n\t"
            "selp.b32 %0, 1, 0, p;\n\t}"
            : "=r"(done) : "r"(mbar) : "memory");
        if (!done) {
            asm volatile(
                "{\n\t.reg .pred P1;\n\t"
                "WL_%=:\n\t"
                "mbarrier.try_wait.parity.acquire.cta.shared::cta.b64 P1, [%0], 0, 0x989680;\n\t"
                "@P1 bra.uni WD_%=;\n\t"
                "bra.uni WL_%=;\n\t"
                "WD_%=:\n\t}"
                :: "r"(mbar) : "memory");
        }
    }

    const int lane = tid & 31;
    const int gw   = blockIdx.x * WARPS_PER_BLOCK + (tid >> 5);
    const int nw   = GRID_X * WARPS_PER_BLOCK;     // 4736 warps

    const int off = lane * 16;          // 16 B per lane: its 8 permuted cols

    const int npairs = ntok >> 1;       // 32768

    int p = gw;
    if (p >= npairs) return;

    int4 xi0 = *reinterpret_cast<const int4*>(x + (long long)(2 * p)     * NUM_HASHES);
    int4 xi1 = *reinterpret_cast<const int4*>(x + (long long)(2 * p + 1) * NUM_HASHES);

    #pragma unroll 1
    for (; p < npairs; p += nw) {
        const int pn = (p + nw < npairs) ? (p + nw) : p;
        const int4 xn0 = *reinterpret_cast<const int4*>(x + (long long)(2 * pn)     * NUM_HASHES);
        const int4 xn1 = *reinterpret_cast<const int4*>(x + (long long)(2 * pn + 1) * NUM_HASHES);

        // per-sample weights as duplicated half2 (LDS.32 broadcast, no cvt)
        const __half2 u0 = s_wh[xi0.x];
        const __half2 u1 = s_wh[xi0.y + 513];
        const __half2 u2 = s_wh[xi0.z + 1026];
        const __half2 u3 = s_wh[xi0.w + 1539];
        const __half2 v0 = s_wh[xi1.x];
        const __half2 v1 = s_wh[xi1.y + 513];
        const __half2 v2 = s_wh[xi1.z + 1026];
        const __half2 v3 = s_wh[xi1.w + 1539];

        // permuted fp16 row bases (idx = x >> 1; 512 B per row)
        const char* p00 = s_emb + ((xi0.x >> 1) << 9);
        const char* p01 = s_emb + ((xi0.y >> 1) << 9);
        const char* p02 = s_emb + ((xi0.z >> 1) << 9);
        const char* p03 = s_emb + ((xi0.w >> 1) << 9);
        const char* p10 = s_emb + ((xi1.x >> 1) << 9);
        const char* p11 = s_emb + ((xi1.y >> 1) << 9);
        const char* p12 = s_emb + ((xi1.z >> 1) << 9);
        const char* p13 = s_emb + ((xi1.w >> 1) << 9);

        // 8 batched LDS.128 gathers (whole warp reads one contiguous 512 B row)
        const uint4 e00 = *reinterpret_cast<const uint4*>(p00 + off);
        const uint4 e01 = *reinterpret_cast<const uint4*>(p01 + off);
        const uint4 e02 = *reinterpret_cast<const uint4*>(p02 + off);
        const uint4 e03 = *reinterpret_cast<const uint4*>(p03 + off);
        const uint4 e10 = *reinterpret_cast<const uint4*>(p10 + off);
        const uint4 e11 = *reinterpret_cast<const uint4*>(p11 + off);
        const uint4 e12 = *reinterpret_cast<const uint4*>(p12 + off);
        const uint4 e13 = *reinterpret_cast<const uint4*>(p13 + off);

        // lane layout of each uint4: .x=(A0,A1) .y=(A2,A3) .z=(B0,B1) .w=(B2,B3)
        #define H2(u) (*reinterpret_cast<const __half2*>(&(u)))

        // token0: half A (cols lane*4..+3), half B (cols 128+lane*4..+3)
        __half2 aAx = __hmul2(H2(e00.x), u0);
        __half2 aAy = __hmul2(H2(e00.y), u0);
        __half2 aBx = __hmul2(H2(e00.z), u0);
        __half2 aBy = __hmul2(H2(e00.w), u0);
        aAx = __hfma2(H2(e01.x), u1, aAx);  aAy = __hfma2(H2(e01.y), u1, aAy);
        aBx = __hfma2(H2(e01.z), u1, aBx);  aBy = __hfma2(H2(e01.w), u1, aBy);
        aAx = __hfma2(H2(e02.x), u2, aAx);  aAy = __hfma2(H2(e02.y), u2, aAy);
        aBx = __hfma2(H2(e02.z), u2, aBx);  aBy = __hfma2(H2(e02.w), u2, aBy);
        aAx = __hfma2(H2(e03.x), u3, aAx);  aAy = __hfma2(H2(e03.y), u3, aAy);
        aBx = __hfma2(H2(e03.z), u3, aBx);  aBy = __hfma2(H2(e03.w), u3, aBy);

        // token1
        __half2 bAx = __hmul2(H2(e10.x), v0);
        __half2 bAy = __hmul2(H2(e10.y), v0);
        __half2 bBx = __hmul2(H2(e10.z), v0);
        __half2 bBy = __hmul2(H2(e10.w), v0);
        bAx = __hfma2(H2(e11.x), v1, bAx);  bAy = __hfma2(H2(e11.y), v1, bAy);
        bBx = __hfma2(H2(e11.z), v1, bBx);  bBy = __hfma2(H2(e11.w), v1, bBy);
        bAx = __hfma2(H2(e12.x), v2, bAx);  bAy = __hfma2(H2(e12.y), v2, bAy);
        bBx = __hfma2(H2(e12.z), v2, bBx);  bBy = __hfma2(H2(e12.w), v2, bBy);
        bAx = __hfma2(H2(e13.x), v3, bAx);  bAy = __hfma2(H2(e13.y), v3, bAy);
        bBx = __hfma2(H2(e13.z), v3, bBx);  bBy = __hfma2(H2(e13.w), v3, bBy);

        #undef H2

        const float2 fA0 = __half22float2(aAx), fA1 = __half22float2(aAy);
        const float2 fB0 = __half22float2(aBx), fB1 = __half22float2(aBy);
        const float2 gA0 = __half22float2(bAx), gA1 = __half22float2(bAy);
        const float2 gB0 = __half22float2(bBx), gB1 = __half22float2(bBy);

        // coalesced stores: lane L writes cols [L*4, L*4+4) of each 128-col half
        float* op = out + (long long)(2 * p) * D + lane * 4;
        *reinterpret_cast<float4*>(op)       = make_float4(fA0.x, fA0.y, fA1.x, fA1.y);
        *reinterpret_cast<float4*>(op + 128) = make_float4(fB0.x, fB0.y, fB1.x, fB1.y);
        *reinterpret_cast<float4*>(op + 256) = make_float4(gA0.x, gA0.y, gA1.x, gA1.y);
        *reinterpret_cast<float4*>(op + 384) = make_float4(gB0.x, gB0.y, gB1.x, gB1.y);

        xi0 = xn0;
        xi1 = xn1;
    }
}

extern "C" void kernel_launch(void* const* d_in, const int* in_sizes, int n_in,
                              void* d_out, int out_size)
{
    const int*   x            = (const int*)d_in[0];
    const float* weight_table = (const float*)d_in[1];
    const float* emb_table    = (const float*)d_in[2];
    float*       out          = (float*)d_out;

    const int ntok = in_sizes[0] / NUM_HASHES;   // 65536

    convert_tables_kernel<<<(EMB_ROWS * D / 2 + 255) / 256, 256>>>(weight_table, emb_table);

    cudaFuncSetAttribute(hash_embedding_kernel,
                         cudaFuncAttributeMaxDynamicSharedMemorySize, SMEM_BYTES);
    hash_embedding_kernel<<<GRID_X, BLOCK_THREADS, SMEM_BYTES>>>(x, out, ntok);
}

// round 15
// speedup vs baseline: 1.0578x; 1.0578x over previous
#include <cuda_runtime.h>
#include <cuda_fp16.h>

// HashEmbedding: out[t, d] = sum_{h=0..3} weight_table[x[t,h] + 513*h] * emb_table[x[t,h]>>1][d]
// x is int32.
// R15: NO SHARED MEMORY. Gathers read the pre-converted, pre-PERMUTED fp16
// table (128 KB) from global via __ldg -> it lives in L1D (228 KB carveout,
// smem=0). This lifts the 32-warp/SM cap of the smem design (main-kernel time
// was invariant at ~15.1us across 2x instruction-count changes -> concurrency-
// limited): now 3 CTAs x 512 = 48 warps/SM, zero prologue, zero syncs.
// x loads / out stores use .cs streaming to protect L1 residency of the table.
// Permuted row layout: lane L's single 16-byte read = cols [L*4..+3] of half A
// and [128+L*4..+3] of half B -> both stores stay perfectly coalesced.

#define NUM_HASHES 4
#define D 256
#define W_TABLE 2052           // 512*4 + 4
#define EMB_ROWS 256
#define BLOCK_THREADS 512
#define WARPS_PER_BLOCK (BLOCK_THREADS / 32)
#define GRID_X 444             // 3 CTAs x 148 SMs

// Pre-converted tables (filled by convert kernel each replay).
__device__ __align__(16) __half2 g_wh2[W_TABLE];                 // duplicated half2 weights
__device__ __align__(16) uint4   g_emb_p[EMB_ROWS * 32];         // permuted rows, 32 uint4/row

// Destination-indexed convert: coalesced writes, near-coalesced reads.
__global__ void convert_tables_kernel(const float* __restrict__ weight_table,
                                      const float* __restrict__ emb_table)
{
    const int i = blockIdx.x * blockDim.x + threadIdx.x;
    if (i < W_TABLE) {
        g_wh2[i] = __float2half2_rn(weight_table[i]);
    }
    if (i < EMB_ROWS * D / 2) {            // one dst half2 per thread
        const int row = i >> 7;            // 128 h2 per row
        const int jr  = i & 127;           // dst h2 index within row
        const int g    = jr >> 2;          // 4-col group
        const int h    = (jr & 3) >> 1;    // which 128-col half
        const int pos2 = jr & 1;
        const int c    = h * 128 + g * 4 + pos2 * 2;    // source column
        const float2 v = *reinterpret_cast<const float2*>(emb_table + row * D + c);
        reinterpret_cast<__half2*>(g_emb_p)[i] = __floats2half2_rn(v.x, v.y);
    }
}

__device__ __forceinline__ int4 ldcs_int4(const int* p) {
    int4 v;
    asm volatile("ld.global.cs.v4.s32 {%0,%1,%2,%3}, [%4];"
                 : "=r"(v.x), "=r"(v.y), "=r"(v.z), "=r"(v.w) : "l"(p));
    return v;
}
__device__ __forceinline__ void stcs_float4(float* p, float4 v) {
    asm volatile("st.global.cs.v4.f32 [%0], {%1,%2,%3,%4};"
                 :: "l"(p), "f"(v.x), "f"(v.y), "f"(v.z), "f"(v.w) : "memory");
}

__global__ __launch_bounds__(BLOCK_THREADS, 3)
void hash_embedding_kernel(const int* __restrict__ x,
                           float* __restrict__ out,
                           int ntok)
{
    const int tid  = threadIdx.x;
    const int lane = tid & 31;
    const int gw   = blockIdx.x * WARPS_PER_BLOCK + (tid >> 5);
    const int nw   = GRID_X * WARPS_PER_BLOCK;       // 7104 warps

    const uint4*   emb = g_emb_p;                    // L1-resident via __ldg
    const __half2* wh  = g_wh2;

    int t = gw;
    if (t >= ntok) return;

    // depth-1 index prefetch (streaming)
    int4 xi = ldcs_int4(x + (long long)t * NUM_HASHES);

    #pragma unroll 1
    for (; t < ntok; t += nw) {
        const int tn = (t + nw < ntok) ? (t + nw) : t;
        const int4 xi_next = ldcs_int4(x + (long long)tn * NUM_HASHES);

        // per-sample weights: duplicated half2, uniform address across warp (L1 hit)
        const __half2 u0 = __ldg(wh + xi.x);
        const __half2 u1 = __ldg(wh + xi.y + 513);
        const __half2 u2 = __ldg(wh + xi.z + 1026);
        const __half2 u3 = __ldg(wh + xi.w + 1539);

        // gathers: whole warp reads one contiguous permuted 512 B row per hash
        // (4 x 128 B lines, L1-hit). Row base in uint4 units = idx*32.
        const uint4 e0 = __ldg(emb + ((xi.x >> 1) << 5) + lane);
        const uint4 e1 = __ldg(emb + ((xi.y >> 1) << 5) + lane);
        const uint4 e2 = __ldg(emb + ((xi.z >> 1) << 5) + lane);
        const uint4 e3 = __ldg(emb + ((xi.w >> 1) << 5) + lane);

        // lane layout of each uint4: .x=(A0,A1) .y=(A2,A3) .z=(B0,B1) .w=(B2,B3)
        #define H2(u) (*reinterpret_cast<const __half2*>(&(u)))
        __half2 aAx = __hmul2(H2(e0.x), u0);
        __half2 aAy = __hmul2(H2(e0.y), u0);
        __half2 aBx = __hmul2(H2(e0.z), u0);
        __half2 aBy = __hmul2(H2(e0.w), u0);
        aAx = __hfma2(H2(e1.x), u1, aAx);  aAy = __hfma2(H2(e1.y), u1, aAy);
        aBx = __hfma2(H2(e1.z), u1, aBx);  aBy = __hfma2(H2(e1.w), u1, aBy);
        aAx = __hfma2(H2(e2.x), u2, aAx);  aAy = __hfma2(H2(e2.y), u2, aAy);
        aBx = __hfma2(H2(e2.z), u2, aBx);  aBy = __hfma2(H2(e2.w), u2, aBy);
        aAx = __hfma2(H2(e3.x), u3, aAx);  aAy = __hfma2(H2(e3.y), u3, aAy);
        aBx = __hfma2(H2(e3.z), u3, aBx);  aBy = __hfma2(H2(e3.w), u3, aBy);
        #undef H2

        const float2 fA0 = __half22float2(aAx), fA1 = __half22float2(aAy);
        const float2 fB0 = __half22float2(aBx), fB1 = __half22float2(aBy);

        // coalesced streaming stores: lane L writes cols [L*4,L*4+4) of each half
        float* op = out + (long long)t * D + lane * 4;
        stcs_float4(op,       make_float4(fA0.x, fA0.y, fA1.x, fA1.y));
        stcs_float4(op + 128, make_float4(fB0.x, fB0.y, fB1.x, fB1.y));

        xi = xi_next;
    }
}

extern "C" void kernel_launch(void* const* d_in, const int* in_sizes, int n_in,
                              void* d_out, int out_size)
{
    const int*   x            = (const int*)d_in[0];
    const float* weight_table = (const float*)d_in[1];
    const float* emb_table    = (const float*)d_in[2];
    float*       out          = (float*)d_out;

    const int ntok = in_sizes[0] / NUM_HASHES;   // 65536

    // maximize L1 carveout (no smem used by the main kernel)
    static bool configured = false;
    if (!configured) {
        cudaFuncSetAttribute(hash_embedding_kernel,
                             cudaFuncAttributePreferredSharedMemoryCarveout, 0);
        configured = true;
    }

    convert_tables_kernel<<<(EMB_ROWS * D / 2 + 255) / 256, 256>>>(weight_table, emb_table);
    hash_embedding_kernel<<<GRID_X, BLOCK_THREADS>>>(x, out, ntok);
}

// round 16
// speedup vs baseline: 1.0759x; 1.0171x over previous
#include <cuda_runtime.h>
#include <cuda_fp16.h>

// HashEmbedding: out[t, d] = sum_{h=0..3} weight_table[x[t,h] + 513*h] * emb_table[x[t,h]>>1][d]
// x is int32.
// R16: SINGLE-LINE memory ops. All prior designs (~15.1us invariant) were bound
// by L1tex within-instruction wavefront replays (2.07 cyc/line on multi-line
// warp-wide ops). Gathers become 16x warp-wide LDG.32 (each exactly one 128 B
// line -> 1 wavefront @ 1.0 cyc), from the NATURAL row-major fp16 table in L1
// (no smem, carveout=0, no permutation). Stores: 4x warp-wide STG.64, each
// covering exactly 2 full 128 B lines (slot s of lane L = output cols
// [64s+2L, 64s+2L+1] -> coalesced). LSU-issue becomes the bound (~18.5K cyc/SM).

#define NUM_HASHES 4
#define D 256
#define W_TABLE 2052           // 512*4 + 4
#define EMB_ROWS 256
#define BLOCK_THREADS 512
#define WARPS_PER_BLOCK (BLOCK_THREADS / 32)
#define GRID_X 444             // 3 CTAs x 148 SMs

// Pre-converted tables (filled by convert kernel each replay). Natural layout.
__device__ __align__(16) __half2 g_wh2[W_TABLE];            // duplicated half2 weights
__device__ __align__(16) __half2 g_emb_h2[EMB_ROWS * 128];  // row-major, 128 h2/row

__global__ void convert_tables_kernel(const float* __restrict__ weight_table,
                                      const float* __restrict__ emb_table)
{
    const int i = blockIdx.x * blockDim.x + threadIdx.x;
    if (i < W_TABLE) {
        g_wh2[i] = __float2half2_rn(weight_table[i]);
    }
    if (i < EMB_ROWS * 128) {   // one dst half2 per thread; fully coalesced
        const float2 v = *reinterpret_cast<const float2*>(emb_table + i * 2);
        g_emb_h2[i] = __floats2half2_rn(v.x, v.y);
    }
}

__device__ __forceinline__ int4 ldcs_int4(const int* p) {
    int4 v;
    asm volatile("ld.global.cs.v4.s32 {%0,%1,%2,%3}, [%4];"
                 : "=r"(v.x), "=r"(v.y), "=r"(v.z), "=r"(v.w) : "l"(p));
    return v;
}
__device__ __forceinline__ void stcs_float2(float* p, float2 v) {
    asm volatile("st.global.cs.v2.f32 [%0], {%1,%2};"
                 :: "l"(p), "f"(v.x), "f"(v.y) : "memory");
}

__global__ __launch_bounds__(BLOCK_THREADS, 3)
void hash_embedding_kernel(const int* __restrict__ x,
                           float* __restrict__ out,
                           int ntok)
{
    const int tid  = threadIdx.x;
    const int lane = tid & 31;
    const int gw   = blockIdx.x * WARPS_PER_BLOCK + (tid >> 5);
    const int nw   = GRID_X * WARPS_PER_BLOCK;       // 7104 warps

    const __half2* emb = g_emb_h2;                   // L1-resident via __ldg
    const __half2* wh  = g_wh2;

    int t = gw;
    if (t >= ntok) return;

    // depth-1 index prefetch (streaming)
    int4 xi = ldcs_int4(x + (long long)t * NUM_HASHES);

    #pragma unroll 1
    for (; t < ntok; t += nw) {
        const int tn = (t + nw < ntok) ? (t + nw) : t;
        const int4 xi_next = ldcs_int4(x + (long long)tn * NUM_HASHES);

        // per-sample weights: duplicated half2, uniform address (1 line each)
        const __half2 u0 = __ldg(wh + xi.x);
        const __half2 u1 = __ldg(wh + xi.y + 513);
        const __half2 u2 = __ldg(wh + xi.z + 1026);
        const __half2 u3 = __ldg(wh + xi.w + 1539);

        // row bases in h2 units (idx = x >> 1; 128 h2 per row)
        const __half2* r0 = emb + ((xi.x >> 1) << 7);
        const __half2* r1 = emb + ((xi.y >> 1) << 7);
        const __half2* r2 = emb + ((xi.z >> 1) << 7);
        const __half2* r3 = emb + ((xi.w >> 1) << 7);

        // 16 single-line gathers: slot s, hash h -> h2 index 32s+lane.
        // Each warp-wide LDG.32 touches exactly one 128 B line (1 wavefront).
        __half2 g0[4], g1[4], g2[4], g3[4];
        #pragma unroll
        for (int s = 0; s < 4; ++s) {
            const int j = (s << 5) + lane;
            g0[s] = __ldg(r0 + j);
            g1[s] = __ldg(r1 + j);
            g2[s] = __ldg(r2 + j);
            g3[s] = __ldg(r3 + j);
        }

        // HFMA2 accumulation per slot
        float2 f[4];
        #pragma unroll
        for (int s = 0; s < 4; ++s) {
            __half2 a = __hmul2(g0[s], u0);
            a = __hfma2(g1[s], u1, a);
            a = __hfma2(g2[s], u2, a);
            a = __hfma2(g3[s], u3, a);
            f[s] = __half22float2(a);
        }

        // 4 warp-wide STG.64: slot s covers output cols [64s .. 64s+63]
        // (lane L -> cols 64s+2L, 64s+2L+1), i.e. 2 full 128 B lines each.
        float* op = out + (long long)t * D + lane * 2;
        #pragma unroll
        for (int s = 0; s < 4; ++s) {
            stcs_float2(op + (s << 6), f[s]);
        }

        xi = xi_next;
    }
}

extern "C" void kernel_launch(void* const* d_in, const int* in_sizes, int n_in,
                              void* d_out, int out_size)
{
    const int*   x            = (const int*)d_in[0];
    const float* weight_table = (const float*)d_in[1];
    const float* emb_table    = (const float*)d_in[2];
    float*       out          = (float*)d_out;

    const int ntok = in_sizes[0] / NUM_HASHES;   // 65536

    // maximize L1 carveout (main kernel uses no smem)
    static bool configured = false;
    if (!configured) {
        cudaFuncSetAttribute(hash_embedding_kernel,
                             cudaFuncAttributePreferredSharedMemoryCarveout, 0);
        configured = true;
    }

    convert_tables_kernel<<<(EMB_ROWS * 128 + 255) / 256, 256>>>(weight_table, emb_table);
    hash_embedding_kernel<<<GRID_X, BLOCK_THREADS>>>(x, out, ntok);
}